// round 14
// baseline (speedup 1.0000x reference)
#include <cuda_runtime.h>
#include <cstdint>

#define Dz 64
#define Hh 128
#define Wf 128
#define CWARPS 4             // max compute warps (2 rows each)
#define NWARPS 5             // 4 compute + 1 producer
#define NS 5                 // pipeline stages
#define VOLS 32
#define NB8 444              // 8-row tiles (waves 0..2)
#define NB4 136              // 4-row tiles (wave 3)
#define NB  (NB8 + NB4)      // 580 blocks, single wave (<= 592 slots)
#define ROWBYTES 512
#define MAXTILEROWS 10       // stage pitch (rows) — fixed for compile-time layout
#define STAGEBYTES (MAXTILEROWS * ROWBYTES)   // 5120 per tensor (pitch)
#define STAGEPAIR  (2 * STAGEBYTES)           // 10240
#define PLANEF (Hh * Wf)
#define DYN_STAGE0 1024
#define DYN_TOTAL (DYN_STAGE0 + NS * STAGEPAIR)   // 52224 -> occ 4

#define NEG1 0xBF800000BF800000ULL

__device__ float g_partial[NB];
__device__ unsigned int g_count;

struct U2 { unsigned long long a, b; };

__device__ __forceinline__ unsigned long long fma2(unsigned long long a,
                                                   unsigned long long b,
                                                   unsigned long long c) {
    unsigned long long d;
    asm("fma.rn.f32x2 %0, %1, %2, %3;" : "=l"(d) : "l"(a), "l"(b), "l"(c));
    return d;
}
__device__ __forceinline__ unsigned long long add2(unsigned long long a,
                                                   unsigned long long b) {
    unsigned long long d;
    asm("add.rn.f32x2 %0, %1, %2;" : "=l"(d) : "l"(a), "l"(b));
    return d;
}
__device__ __forceinline__ float lo32(unsigned long long v) { return __uint_as_float((unsigned)v); }
__device__ __forceinline__ float hi32(unsigned long long v) { return __uint_as_float((unsigned)(v >> 32)); }

__device__ __forceinline__ uint32_t smem_u32(const void* p) {
    uint32_t a;
    asm("{ .reg .u64 t; cvta.to.shared.u64 t, %1; cvt.u32.u64 %0, t; }" : "=r"(a) : "l"(p));
    return a;
}
__device__ __forceinline__ void mbar_init(uint32_t a, uint32_t cnt) {
    asm volatile("mbarrier.init.shared.b64 [%0], %1;" :: "r"(a), "r"(cnt) : "memory");
}
__device__ __forceinline__ void mbar_expect_tx(uint32_t a, uint32_t bytes) {
    asm volatile("mbarrier.arrive.expect_tx.shared.b64 _, [%0], %1;" :: "r"(a), "r"(bytes) : "memory");
}
__device__ __forceinline__ void mbar_arrive(uint32_t a) {
    asm volatile("mbarrier.arrive.shared.b64 _, [%0];" :: "r"(a) : "memory");
}
__device__ __forceinline__ void mbar_wait(uint32_t a, uint32_t parity) {
    uint32_t done;
    asm volatile("{\n\t.reg .pred p;\n\t"
                 "mbarrier.try_wait.parity.acquire.cta.shared::cta.b64 p, [%1], %2;\n\t"
                 "selp.b32 %0, 1, 0, p;\n\t}"
                 : "=r"(done) : "r"(a), "r"(parity) : "memory");
    if (!done) {
        asm volatile("{\n\t.reg .pred P1;\n\t"
                     "W_%=:\n\t"
                     "mbarrier.try_wait.parity.acquire.cta.shared::cta.b64 P1, [%0], %1, 0x989680;\n\t"
                     "@P1 bra.uni D_%=;\n\t"
                     "bra.uni W_%=;\n\t"
                     "D_%=:\n\t}"
                     :: "r"(a), "r"(parity) : "memory");
    }
}
__device__ __forceinline__ void bulk_g2s(uint32_t dst, const void* src, uint32_t bytes, uint32_t mbar) {
    asm volatile("cp.async.bulk.shared::cta.global.mbarrier::complete_tx::bytes [%0], [%1], %2, [%3];"
                 :: "r"(dst), "l"(src), "r"(bytes), "r"(mbar) : "memory");
}

__global__ __launch_bounds__(NWARPS * 32, 4)
void gradloss_kernel(const float* __restrict__ xf, const float* __restrict__ tf,
                     float* __restrict__ out)
{
    extern __shared__ char dynsm[];
    const uint32_t smb = smem_u32(dynsm);
    __shared__ float wsum[CWARPS];
    __shared__ int   isLast;

    const int tid  = threadIdx.x;
    const int lane = tid & 31;
    const int warp = tid >> 5;
    const int bid  = blockIdx.x;

    // ---- mixed tile sizes: bids 0..443 -> 8 rows; 444..579 -> 4 rows ----
    int r0, sz;
    if (bid < NB8) { sz = 8; r0 = bid * 8; }
    else           { sz = 4; r0 = NB8 * 8 + (bid - NB8) * 4; }
    const int v  = r0 >> 7;       // volume (no tile straddles a volume: 4|128, 8|128)
    const int h0 = r0 & 127;
    const int CWACT = sz >> 1;    // active compute warps (2 rows each)
    const int SROWS = sz + 2;     // staged rows (with halo)
    const uint32_t STGB = (uint32_t)SROWS * ROWBYTES;   // runtime stage bytes/tensor

    int hStart = h0 - 1;
    if (hStart < 0) hStart = 0;
    if (hStart > Hh - SROWS) hStart = Hh - SROWS;

    const float* xsrc0 = xf + (size_t)v * Dz * PLANEF + (size_t)hStart * Wf;
    const float* tsrc0 = tf + (size_t)v * Dz * PLANEF + (size_t)hStart * Wf;

    #define FULLB(s)  (smb + (uint32_t)(s) * 16u)
    #define EMPTYB(s) (smb + (uint32_t)(s) * 16u + 8u)
    #define XS(s)     ((const ulonglong2*)(dynsm + DYN_STAGE0 + (s) * STAGEPAIR))
    #define TS(s)     ((const ulonglong2*)(dynsm + DYN_STAGE0 + (s) * STAGEPAIR + STAGEBYTES))

    if (tid == 0) {
        #pragma unroll
        for (int s = 0; s < NS; ++s) { mbar_init(FULLB(s), 1); mbar_init(EMPTYB(s), (uint32_t)CWACT); }
    }
    __syncthreads();

    float acc = 0.0f;

    if (warp == CWARPS) {
        // ===== producer: lane 0 only, tight serial loop =====
        if (lane == 0) {
            int s = 0, kpar = 0;
            uint32_t xaddr = smb + DYN_STAGE0;
            #pragma unroll 1
            for (int ai = 0; ai < Dz; ++ai) {
                if (ai >= NS) mbar_wait(EMPTYB(s), kpar ^ 1);
                mbar_expect_tx(FULLB(s), 2u * STGB);
                const size_t off = (size_t)ai * PLANEF;
                bulk_g2s(xaddr,              xsrc0 + off, STGB, FULLB(s));
                bulk_g2s(xaddr + STAGEBYTES, tsrc0 + off, STGB, FULLB(s));
                ++s; xaddr += STAGEPAIR;
                if (s == NS) { s = 0; kpar ^= 1; xaddr = smb + DYN_STAGE0; }
            }
        }
    } else if (warp < CWACT) {
        // ===== compute warps: rows gh0 = h0+2w, gh1 = gh0+1 =====
        const int gh0 = h0 + 2 * warp;
        const int gh1 = gh0 + 1;
        const int lc0 = gh0 - hStart;
        const int lc1 = lc0 + 1;
        const int lm0 = (gh0 == 0)      ? lc0 : lc0 - 1;
        const int lp1 = (gh1 == Hh - 1) ? lc1 : lc1 + 1;
        const int c0Off  = lc0 * 32 + lane;
        const int c1Off  = lc1 * 32 + lane;
        const int hm0Off = lm0 * 32 + lane;
        const int hp1Off = lp1 * 32 + lane;

        U2 u_m0, u_c0, u_p0, u_m1, u_c1, u_p1;
        u_m0.a = u_m0.b = 0; u_c0.a = u_c0.b = 0; u_p0.a = u_p0.b = 0;
        u_m1.a = u_m1.b = 0; u_c1.a = u_c1.b = 0; u_p1.a = u_p1.b = 0;

        unsigned long long acc2D = 0, acc2H0 = 0, acc2H1 = 0;
        float accWx = 0.f, accWm = 0.f, accWw = 0.f;

        #define FOLD_CENTER(S)                                                   \
            { ulonglong2 xa = XS(S)[c0Off], ta = TS(S)[c0Off];                   \
              ulonglong2 xb = XS(S)[c1Off], tb = TS(S)[c1Off];                   \
              u_m0 = u_c0; u_c0 = u_p0;                                          \
              u_p0.a = fma2(ta.x, NEG1, xa.x); u_p0.b = fma2(ta.y, NEG1, xa.y);  \
              u_m1 = u_c1; u_c1 = u_p1;                                          \
              u_p1.a = fma2(tb.x, NEG1, xb.x); u_p1.b = fma2(tb.y, NEG1, xb.y); }

        #define D_INT() do {                                                     \
            unsigned long long d0a = fma2(u_m0.a, NEG1, u_p0.a);                 \
            unsigned long long d0b = fma2(u_m0.b, NEG1, u_p0.b);                 \
            acc2D = fma2(d0a, d0a, acc2D); acc2D = fma2(d0b, d0b, acc2D);        \
            unsigned long long d1a = fma2(u_m1.a, NEG1, u_p1.a);                 \
            unsigned long long d1b = fma2(u_m1.b, NEG1, u_p1.b);                 \
            acc2D = fma2(d1a, d1a, acc2D); acc2D = fma2(d1b, d1b, acc2D);        \
        } while (0)

        #define D_EDGE(H0, L0, H1, L1) do {                                      \
            unsigned long long d0a = fma2((L0).a, NEG1, (H0).a); d0a = add2(d0a, d0a); \
            unsigned long long d0b = fma2((L0).b, NEG1, (H0).b); d0b = add2(d0b, d0b); \
            acc2D = fma2(d0a, d0a, acc2D); acc2D = fma2(d0b, d0b, acc2D);        \
            unsigned long long d1a = fma2((L1).a, NEG1, (H1).a); d1a = add2(d1a, d1a); \
            unsigned long long d1b = fma2((L1).b, NEG1, (H1).b); d1b = add2(d1b, d1b); \
            acc2D = fma2(d1a, d1a, acc2D); acc2D = fma2(d1b, d1b, acc2D);        \
        } while (0)

        #define WROW(C) do {                                                     \
            float f0 = lo32((C).a), f1 = hi32((C).a);                            \
            float f2 = lo32((C).b), f3 = hi32((C).b);                            \
            float wl = __shfl_up_sync(0xffffffffu, f3, 1);                       \
            float wr = __shfl_down_sync(0xffffffffu, f0, 1);                     \
            float ax = (lane == 0)  ? f0 : wl;                                   \
            float aw = (lane == 31) ? f3 : wr;                                   \
            float dx = f1 - ax, dy = f2 - f0, dz = f3 - f1, dw = aw - f2;        \
            accWx = fmaf(dx, dx, accWx); accWm = fmaf(dy, dy, accWm);            \
            accWm = fmaf(dz, dz, accWm); accWw = fmaf(dw, dw, accWw);            \
        } while (0)

        #define HW(SQ, C0, C1) do {                                              \
            ulonglong2 xm_ = XS(SQ)[hm0Off], tm_ = TS(SQ)[hm0Off];               \
            ulonglong2 xq_ = XS(SQ)[hp1Off], tq_ = TS(SQ)[hp1Off];               \
            unsigned long long hma = fma2(tm_.x, NEG1, xm_.x);                   \
            unsigned long long hmb = fma2(tm_.y, NEG1, xm_.y);                   \
            unsigned long long hpa = fma2(tq_.x, NEG1, xq_.x);                   \
            unsigned long long hpb = fma2(tq_.y, NEG1, xq_.y);                   \
            unsigned long long e0a = fma2(hma, NEG1, (C1).a);                    \
            unsigned long long e0b = fma2(hmb, NEG1, (C1).b);                    \
            acc2H0 = fma2(e0a, e0a, acc2H0); acc2H0 = fma2(e0b, e0b, acc2H0);    \
            unsigned long long e1a = fma2((C0).a, NEG1, hpa);                    \
            unsigned long long e1b = fma2((C0).b, NEG1, hpb);                    \
            acc2H1 = fma2(e1a, e1a, acc2H1); acc2H1 = fma2(e1b, e1b, acc2H1);    \
            WROW(C0); WROW(C1);                                                  \
        } while (0)

        #define RELEASE(SP) do {                                                 \
            __syncwarp();                                                        \
            if (lane == 0) mbar_arrive(EMPTYB(SP));                              \
        } while (0)

        // ---- peel (ai = 0..3, parity 0) ----
        {   mbar_wait(FULLB(0), 0); FOLD_CENTER(0); }
        {   mbar_wait(FULLB(1), 0); FOLD_CENTER(1);
            D_EDGE(u_p0, u_c0, u_p1, u_c1);
            HW(0, u_c0, u_c1); RELEASE(0); }
        {   mbar_wait(FULLB(2), 0); FOLD_CENTER(2);
            D_INT(); HW(1, u_c0, u_c1); RELEASE(1); }
        {   mbar_wait(FULLB(3), 0); FOLD_CENTER(3);
            D_INT(); HW(2, u_c0, u_c1); RELEASE(2); }

        // ---- main: 12 groups of 5 (ai = 4..63); stage pattern {4,0,1,2,3} ----
        #pragma unroll 1
        for (int g = 0; g < 12; ++g) {
            const uint32_t pg  = g & 1;
            const uint32_t pg1 = (g + 1) & 1;
            {   mbar_wait(FULLB(4), pg);  FOLD_CENTER(4);
                D_INT(); HW(3, u_c0, u_c1); RELEASE(3); }
            {   mbar_wait(FULLB(0), pg1); FOLD_CENTER(0);
                D_INT(); HW(4, u_c0, u_c1); RELEASE(4); }
            {   mbar_wait(FULLB(1), pg1); FOLD_CENTER(1);
                D_INT(); HW(0, u_c0, u_c1); RELEASE(0); }
            {   mbar_wait(FULLB(2), pg1); FOLD_CENTER(2);
                D_INT(); HW(1, u_c0, u_c1); RELEASE(1); }
            {   mbar_wait(FULLB(3), pg1); FOLD_CENTER(3);
                D_INT(); HW(2, u_c0, u_c1); RELEASE(2); }
        }

        // ---- tail: plane 63 ----
        D_EDGE(u_p0, u_c0, u_p1, u_c1);
        HW(3, u_p0, u_p1);

        const float sH0 = (gh0 == 0)      ? 1.0f : 0.25f;
        const float sH1 = (gh1 == Hh - 1) ? 1.0f : 0.25f;
        const float sx2 = (lane == 0)  ? 1.0f : 0.25f;
        const float sw2 = (lane == 31) ? 1.0f : 0.25f;
        acc = 0.25f * (lo32(acc2D) + hi32(acc2D))
            + sH0   * (lo32(acc2H0) + hi32(acc2H0))
            + sH1   * (lo32(acc2H1) + hi32(acc2H1))
            + 0.25f * accWm + sx2 * accWx + sw2 * accWw;
    }
    // (warps in [CWACT, CWARPS) on 4-row tiles are idle: acc = 0, no mbarrier ops)

    // ================= block reduction (all 5 warps) =================
    #pragma unroll
    for (int off = 16; off > 0; off >>= 1)
        acc += __shfl_down_sync(0xffffffffu, acc, off);
    if (warp < CWARPS && lane == 0) wsum[warp] = acc;
    __syncthreads();
    if (tid == 0) {
        float s = 0.0f;
        #pragma unroll
        for (int i = 0; i < CWARPS; ++i) s += wsum[i];
        g_partial[bid] = s;
        __threadfence();
        unsigned old = atomicAdd(&g_count, 1u);
        isLast = (old == NB - 1) ? 1 : 0;
    }
    __syncthreads();

    if (isLast) {
        __threadfence();
        const volatile float* gp = g_partial;
        double sd = 0.0;
        for (int i = tid; i < NB; i += NWARPS * 32) sd += (double)gp[i];
        #pragma unroll
        for (int off = 16; off > 0; off >>= 1)
            sd += __shfl_down_sync(0xffffffffu, sd, off);
        __shared__ double dsum[NWARPS];
        if (lane == 0) dsum[warp] = sd;
        __syncthreads();
        if (tid == 0) {
            double tot = 0.0;
            #pragma unroll
            for (int i = 0; i < NWARPS; ++i) tot += dsum[i];
            out[0] = (float)(tot * (1.0 / 8388608.0));
            g_count = 0;
        }
    }
}

extern "C" void kernel_launch(void* const* d_in, const int* in_sizes, int n_in,
                              void* d_out, int out_size)
{
    const float* x = (const float*)d_in[0];
    const float* t = (const float*)d_in[1];

    cudaFuncSetAttribute(gradloss_kernel,
                         cudaFuncAttributeMaxDynamicSharedMemorySize, DYN_TOTAL);

    gradloss_kernel<<<NB, NWARPS * 32, DYN_TOTAL>>>(x, t, (float*)d_out);
}

// round 15
// speedup vs baseline: 1.0529x; 1.0529x over previous
#include <cuda_runtime.h>
#include <cstdint>

#define Dz 64
#define Hh 128
#define Wf 128               // floats per row
#define TROWS 8              // rows per block tile
#define CWARPS 4             // compute warps (2 rows each)
#define NWARPS 5             // 4 compute + 1 producer
#define NS 5                 // pipeline stages
#define VOLS 32              // B*C
#define NB ((Hh / TROWS) * VOLS)   // 512 blocks — single wave at occ 4
#define ROWBYTES (Wf * 4)          // 512
#define TILEROWS (TROWS + 2)       // 10
#define STAGEBYTES (TILEROWS * ROWBYTES)   // 5120 per tensor
#define STAGEPAIR  (2 * STAGEBYTES)        // 10240
#define PLANEF (Hh * Wf)           // 16384 floats per plane
#define DYN_STAGE0 1024
#define DYN_TOTAL (DYN_STAGE0 + NS * STAGEPAIR)   // 52224 -> 4 CTAs = 204 KB

#define NEG1 0xBF800000BF800000ULL   // (-1.f, -1.f) packed

__device__ double g_acc;           // zero-initialized; self-resets each call
__device__ unsigned int g_count;

struct U2 { unsigned long long a, b; };

__device__ __forceinline__ unsigned long long fma2(unsigned long long a,
                                                   unsigned long long b,
                                                   unsigned long long c) {
    unsigned long long d;
    asm("fma.rn.f32x2 %0, %1, %2, %3;" : "=l"(d) : "l"(a), "l"(b), "l"(c));
    return d;
}
__device__ __forceinline__ unsigned long long add2(unsigned long long a,
                                                   unsigned long long b) {
    unsigned long long d;
    asm("add.rn.f32x2 %0, %1, %2;" : "=l"(d) : "l"(a), "l"(b));
    return d;
}
__device__ __forceinline__ float lo32(unsigned long long v) { return __uint_as_float((unsigned)v); }
__device__ __forceinline__ float hi32(unsigned long long v) { return __uint_as_float((unsigned)(v >> 32)); }

__device__ __forceinline__ uint32_t smem_u32(const void* p) {
    uint32_t a;
    asm("{ .reg .u64 t; cvta.to.shared.u64 t, %1; cvt.u32.u64 %0, t; }" : "=r"(a) : "l"(p));
    return a;
}
__device__ __forceinline__ void mbar_init(uint32_t a, uint32_t cnt) {
    asm volatile("mbarrier.init.shared.b64 [%0], %1;" :: "r"(a), "r"(cnt) : "memory");
}
__device__ __forceinline__ void mbar_expect_tx(uint32_t a, uint32_t bytes) {
    asm volatile("mbarrier.arrive.expect_tx.shared.b64 _, [%0], %1;" :: "r"(a), "r"(bytes) : "memory");
}
__device__ __forceinline__ void mbar_arrive(uint32_t a) {
    asm volatile("mbarrier.arrive.shared.b64 _, [%0];" :: "r"(a) : "memory");
}
__device__ __forceinline__ void mbar_wait(uint32_t a, uint32_t parity) {
    uint32_t done;
    asm volatile("{\n\t.reg .pred p;\n\t"
                 "mbarrier.try_wait.parity.acquire.cta.shared::cta.b64 p, [%1], %2;\n\t"
                 "selp.b32 %0, 1, 0, p;\n\t}"
                 : "=r"(done) : "r"(a), "r"(parity) : "memory");
    if (!done) {
        asm volatile("{\n\t.reg .pred P1;\n\t"
                     "W_%=:\n\t"
                     "mbarrier.try_wait.parity.acquire.cta.shared::cta.b64 P1, [%0], %1, 0x989680;\n\t"
                     "@P1 bra.uni D_%=;\n\t"
                     "bra.uni W_%=;\n\t"
                     "D_%=:\n\t}"
                     :: "r"(a), "r"(parity) : "memory");
    }
}
__device__ __forceinline__ void bulk_g2s(uint32_t dst, const void* src, uint32_t bytes, uint32_t mbar) {
    asm volatile("cp.async.bulk.shared::cta.global.mbarrier::complete_tx::bytes [%0], [%1], %2, [%3];"
                 :: "r"(dst), "l"(src), "r"(bytes), "r"(mbar) : "memory");
}

__global__ __launch_bounds__(NWARPS * 32, 4)
void gradloss_kernel(const float* __restrict__ xf, const float* __restrict__ tf,
                     float* __restrict__ out)
{
    extern __shared__ char dynsm[];
    const uint32_t smb = smem_u32(dynsm);
    __shared__ float wsum[CWARPS];

    const int tid  = threadIdx.x;
    const int lane = tid & 31;
    const int warp = tid >> 5;
    const int h0   = blockIdx.x * TROWS;
    const int v    = blockIdx.y;

    int hStart = h0 - 1;
    if (hStart < 0) hStart = 0;
    if (hStart > Hh - TILEROWS) hStart = Hh - TILEROWS;

    const float* xsrc0 = xf + (size_t)v * Dz * PLANEF + (size_t)hStart * Wf;
    const float* tsrc0 = tf + (size_t)v * Dz * PLANEF + (size_t)hStart * Wf;

    #define FULLB(s)  (smb + (uint32_t)(s) * 16u)
    #define EMPTYB(s) (smb + (uint32_t)(s) * 16u + 8u)
    #define XS(s)     ((const ulonglong2*)(dynsm + DYN_STAGE0 + (s) * STAGEPAIR))
    #define TS(s)     ((const ulonglong2*)(dynsm + DYN_STAGE0 + (s) * STAGEPAIR + STAGEBYTES))

    if (tid == 0) {
        #pragma unroll
        for (int s = 0; s < NS; ++s) { mbar_init(FULLB(s), 1); mbar_init(EMPTYB(s), CWARPS); }
    }
    __syncthreads();

    float acc = 0.0f;

    if (warp == CWARPS) {
        // ===== producer: lane 0 ONLY, tight serial loop =====
        if (lane == 0) {
            int s = 0, kpar = 0;   // kpar = (ai/NS)&1
            uint32_t xaddr = smb + DYN_STAGE0;
            #pragma unroll 1
            for (int ai = 0; ai < Dz; ++ai) {
                if (ai >= NS) mbar_wait(EMPTYB(s), kpar ^ 1);
                mbar_expect_tx(FULLB(s), 2u * STAGEBYTES);
                const size_t off = (size_t)ai * PLANEF;
                bulk_g2s(xaddr,              xsrc0 + off, STAGEBYTES, FULLB(s));
                bulk_g2s(xaddr + STAGEBYTES, tsrc0 + off, STAGEBYTES, FULLB(s));
                ++s; xaddr += STAGEPAIR;
                if (s == NS) { s = 0; kpar ^= 1; xaddr = smb + DYN_STAGE0; }
            }
        }
    } else {
        // ========= compute warps (0..3): rows gh0 = h0+2w, gh1 = gh0+1 =========
        const int gh0 = h0 + 2 * warp;
        const int gh1 = gh0 + 1;
        const int lc0 = gh0 - hStart;
        const int lc1 = lc0 + 1;
        // clamped outer-halo rows (inner halo = other row's center, kept in regs)
        const int lm0 = (gh0 == 0)      ? lc0 : lc0 - 1;
        const int lp1 = (gh1 == Hh - 1) ? lc1 : lc1 + 1;
        const int c0Off  = lc0 * 32 + lane;   // ulonglong2 units
        const int c1Off  = lc1 * 32 + lane;
        const int hm0Off = lm0 * 32 + lane;
        const int hp1Off = lp1 * 32 + lane;

        U2 u_m0, u_c0, u_p0, u_m1, u_c1, u_p1;
        u_m0.a = u_m0.b = 0; u_c0.a = u_c0.b = 0; u_p0.a = u_p0.b = 0;
        u_m1.a = u_m1.b = 0; u_c1.a = u_c1.b = 0; u_p1.a = u_p1.b = 0;

        unsigned long long acc2D = 0, acc2H0 = 0, acc2H1 = 0;
        float accWx = 0.f, accWm = 0.f, accWw = 0.f;

        #define FOLD_CENTER(S)                                                   \
            { ulonglong2 xa = XS(S)[c0Off], ta = TS(S)[c0Off];                   \
              ulonglong2 xb = XS(S)[c1Off], tb = TS(S)[c1Off];                   \
              u_m0 = u_c0; u_c0 = u_p0;                                          \
              u_p0.a = fma2(ta.x, NEG1, xa.x); u_p0.b = fma2(ta.y, NEG1, xa.y);  \
              u_m1 = u_c1; u_c1 = u_p1;                                          \
              u_p1.a = fma2(tb.x, NEG1, xb.x); u_p1.b = fma2(tb.y, NEG1, xb.y); }

        #define D_INT() do {                                                     \
            unsigned long long d0a = fma2(u_m0.a, NEG1, u_p0.a);                 \
            unsigned long long d0b = fma2(u_m0.b, NEG1, u_p0.b);                 \
            acc2D = fma2(d0a, d0a, acc2D); acc2D = fma2(d0b, d0b, acc2D);        \
            unsigned long long d1a = fma2(u_m1.a, NEG1, u_p1.a);                 \
            unsigned long long d1b = fma2(u_m1.b, NEG1, u_p1.b);                 \
            acc2D = fma2(d1a, d1a, acc2D); acc2D = fma2(d1b, d1b, acc2D);        \
        } while (0)

        // one-sided D, pre-doubled: (2g)^2*0.25 == g^2 under the 0.25 scale
        #define D_EDGE(H0, L0, H1, L1) do {                                      \
            unsigned long long d0a = fma2((L0).a, NEG1, (H0).a); d0a = add2(d0a, d0a); \
            unsigned long long d0b = fma2((L0).b, NEG1, (H0).b); d0b = add2(d0b, d0b); \
            acc2D = fma2(d0a, d0a, acc2D); acc2D = fma2(d0b, d0b, acc2D);        \
            unsigned long long d1a = fma2((L1).a, NEG1, (H1).a); d1a = add2(d1a, d1a); \
            unsigned long long d1b = fma2((L1).b, NEG1, (H1).b); d1b = add2(d1b, d1b); \
            acc2D = fma2(d1a, d1a, acc2D); acc2D = fma2(d1b, d1b, acc2D);        \
        } while (0)

        #define WROW(C) do {                                                     \
            float f0 = lo32((C).a), f1 = hi32((C).a);                            \
            float f2 = lo32((C).b), f3 = hi32((C).b);                            \
            float wl = __shfl_up_sync(0xffffffffu, f3, 1);                       \
            float wr = __shfl_down_sync(0xffffffffu, f0, 1);                     \
            float ax = (lane == 0)  ? f0 : wl;                                   \
            float aw = (lane == 31) ? f3 : wr;                                   \
            float dx = f1 - ax, dy = f2 - f0, dz = f3 - f1, dw = aw - f2;        \
            accWx = fmaf(dx, dx, accWx); accWm = fmaf(dy, dy, accWm);            \
            accWm = fmaf(dz, dz, accWm); accWw = fmaf(dw, dw, accWw);            \
        } while (0)

        // H+W for plane in stage SQ with centers C0, C1:
        // row0: hp = C1 (regs), hm = outer halo (clamped);
        // row1: hm = C0 (regs), hp = outer halo (clamped).
        #define HW(SQ, C0, C1) do {                                              \
            ulonglong2 xm_ = XS(SQ)[hm0Off], tm_ = TS(SQ)[hm0Off];               \
            ulonglong2 xq_ = XS(SQ)[hp1Off], tq_ = TS(SQ)[hp1Off];               \
            unsigned long long hma = fma2(tm_.x, NEG1, xm_.x);                   \
            unsigned long long hmb = fma2(tm_.y, NEG1, xm_.y);                   \
            unsigned long long hpa = fma2(tq_.x, NEG1, xq_.x);                   \
            unsigned long long hpb = fma2(tq_.y, NEG1, xq_.y);                   \
            unsigned long long e0a = fma2(hma, NEG1, (C1).a);                    \
            unsigned long long e0b = fma2(hmb, NEG1, (C1).b);                    \
            acc2H0 = fma2(e0a, e0a, acc2H0); acc2H0 = fma2(e0b, e0b, acc2H0);    \
            unsigned long long e1a = fma2((C0).a, NEG1, hpa);                    \
            unsigned long long e1b = fma2((C0).b, NEG1, hpb);                    \
            acc2H1 = fma2(e1a, e1a, acc2H1); acc2H1 = fma2(e1b, e1b, acc2H1);    \
            WROW(C0); WROW(C1);                                                  \
        } while (0)

        #define RELEASE(SP) do {                                                 \
            __syncwarp();                                                        \
            if (lane == 0) mbar_arrive(EMPTYB(SP));                              \
        } while (0)

        // ---- peel (ai = 0..3, fill #1, parity 0) ----
        {   mbar_wait(FULLB(0), 0); FOLD_CENTER(0); }                 // ai=0
        {   mbar_wait(FULLB(1), 0); FOLD_CENTER(1);                   // ai=1: plane 0 (edge)
            D_EDGE(u_p0, u_c0, u_p1, u_c1);
            HW(0, u_c0, u_c1); RELEASE(0); }
        {   mbar_wait(FULLB(2), 0); FOLD_CENTER(2);                   // ai=2: plane 1
            D_INT(); HW(1, u_c0, u_c1); RELEASE(1); }
        {   mbar_wait(FULLB(3), 0); FOLD_CENTER(3);                   // ai=3: plane 2
            D_INT(); HW(2, u_c0, u_c1); RELEASE(2); }

        // ---- main: 12 groups of 5 (ai = 4..63); stage pattern {4,0,1,2,3} ----
        #pragma unroll 1
        for (int g = 0; g < 12; ++g) {
            const uint32_t pg  = g & 1;
            const uint32_t pg1 = (g + 1) & 1;
            {   mbar_wait(FULLB(4), pg);  FOLD_CENTER(4);
                D_INT(); HW(3, u_c0, u_c1); RELEASE(3); }
            {   mbar_wait(FULLB(0), pg1); FOLD_CENTER(0);
                D_INT(); HW(4, u_c0, u_c1); RELEASE(4); }
            {   mbar_wait(FULLB(1), pg1); FOLD_CENTER(1);
                D_INT(); HW(0, u_c0, u_c1); RELEASE(0); }
            {   mbar_wait(FULLB(2), pg1); FOLD_CENTER(2);
                D_INT(); HW(1, u_c0, u_c1); RELEASE(1); }
            {   mbar_wait(FULLB(3), pg1); FOLD_CENTER(3);
                D_INT(); HW(2, u_c0, u_c1); RELEASE(2); }
        }

        // ---- tail: plane 63 (centers u_p0/u_p1, halos in stage 3 — never released) ----
        D_EDGE(u_p0, u_c0, u_p1, u_c1);
        HW(3, u_p0, u_p1);

        // ---- hoisted scales (gh0 even => gh0!=127; gh1 odd => gh1!=0) ----
        const float sH0 = (gh0 == 0)      ? 1.0f : 0.25f;
        const float sH1 = (gh1 == Hh - 1) ? 1.0f : 0.25f;
        const float sx2 = (lane == 0)  ? 1.0f : 0.25f;
        const float sw2 = (lane == 31) ? 1.0f : 0.25f;
        acc = 0.25f * (lo32(acc2D) + hi32(acc2D))
            + sH0   * (lo32(acc2H0) + hi32(acc2H0))
            + sH1   * (lo32(acc2H1) + hi32(acc2H1))
            + 0.25f * accWm + sx2 * accWx + sw2 * accWw;
    }

    // ====== block reduction -> one double atomic per block (off critical path) ======
    #pragma unroll
    for (int off = 16; off > 0; off >>= 1)
        acc += __shfl_down_sync(0xffffffffu, acc, off);
    if (warp < CWARPS && lane == 0) wsum[warp] = acc;
    __syncthreads();
    if (tid == 0) {
        float s = 0.0f;
        #pragma unroll
        for (int i = 0; i < CWARPS; ++i) s += wsum[i];
        atomicAdd(&g_acc, (double)s);
        __threadfence();
        unsigned old = atomicAdd(&g_count, 1u);
        if (old == NB - 1) {
            // all 512 block-atomics are globally visible (threadfence + count order)
            double tot = g_acc;
            out[0] = (float)(tot * (1.0 / 8388608.0));   // / (B*D*H*W)
            g_acc   = 0.0;                               // reset for graph replay
            g_count = 0;
        }
    }
}

extern "C" void kernel_launch(void* const* d_in, const int* in_sizes, int n_in,
                              void* d_out, int out_size)
{
    const float* x = (const float*)d_in[0];
    const float* t = (const float*)d_in[1];

    cudaFuncSetAttribute(gradloss_kernel,
                         cudaFuncAttributeMaxDynamicSharedMemorySize, DYN_TOTAL);

    dim3 grid(Hh / TROWS, VOLS);          // 16 x 32 = 512 blocks — single wave
    gradloss_kernel<<<grid, NWARPS * 32, DYN_TOTAL>>>(x, t, (float*)d_out);
}